// round 3
// baseline (speedup 1.0000x reference)
#include <cuda_runtime.h>
#include <math.h>
#include <stdint.h>

// ---------------- problem constants ----------------
#define T_STEPS 64
#define B_      32
#define D_      1024
#define L_      2
#define MEM_    35
#define NTOK_   32000
#define HEADS_  2
#define DK_     512
#define BD      (B_*D_)            // 32768
#define MB      (MEM_*B_)          // 1120
#define EPS_    1e-6f
#define SCALE_  0.04419417382415922f  // 1/sqrt(512)

// output offsets (floats): decoded, h, c, H, C
#define OFF_h   ((size_t)T_STEPS*B_*NTOK_)
#define OFF_c   (OFF_h + (size_t)L_*BD)
#define OFF_H   (OFF_c + (size_t)L_*BD)
#define OFF_C   (OFF_H + (size_t)L_*MEM_*BD)

// ---------------- device scratch (no cudaMalloc allowed) ----------------
__device__ float g_e[BD];
__device__ float g_eln[BD];
__device__ float g_q[BD];
__device__ float g_scores[HEADS_*B_*MB];
__device__ float g_attnw[HEADS_*B_*MB];
__device__ float g_att[BD];
__device__ float g_o[BD];
__device__ float g_hin[L_*BD];
__device__ float g_gates[B_*4*D_];
__device__ float g_h[L_*BD];
__device__ float g_c[L_*BD];
__device__ float g_KC[MEM_*BD];            // K cache, row = slot*B + b
__device__ float g_VC[MEM_*BD];
__device__ float g_X[T_STEPS*BD];          // last-layer h per step (decode input)
__device__ float g_histh[T_STEPS*L_*BD];
__device__ float g_histc[T_STEPS*L_*BD];

// ---------------- packed f32x2 FMA helpers ----------------
__device__ __forceinline__ void fma2(unsigned long long &c, unsigned long long a,
                                     unsigned long long b) {
    asm("fma.rn.f32x2 %0, %1, %2, %0;" : "+l"(c) : "l"(a), "l"(b));
}
__device__ __forceinline__ float2 unpk(unsigned long long v) {
    float2 f;
    asm("mov.b64 {%0,%1}, %2;" : "=f"(f.x), "=f"(f.y) : "l"(v));
    return f;
}
__device__ __forceinline__ float sigf(float x) { return 1.f/(1.f+expf(-x)); }

// ---------------- generic fp32 GEMM ----------------
// BLAYN=false: out[m,n] = sum_k A[m,k]*W[n,k]   (W row-major [N,K], ld=ldw)
// BLAYN=true : out[m,n] = sum_k A[m,k]*W[k,n]   (W row-major [K,N], ld=ldw)
// Optional second (A1,W1) pair summed in, plus bias0+bias1.
// M multiple of 32 (exact), K multiple of 16, N guarded.
// blockIdx.z adds strides zA/zW/zO.
#define BK 16
template<int BN, bool BLAYN>
__global__ void __launch_bounds__(256) gemm_k(
    const float* __restrict__ A0, const float* __restrict__ W0,
    const float* __restrict__ A1, const float* __restrict__ W1,
    const float* __restrict__ bias0, const float* __restrict__ bias1,
    float* __restrict__ out,
    int M, int N, int K, int lda, int ldw, int ldo,
    int zA, int zW, int zO)
{
    constexpr int TN  = BN/32;   // output cols per thread (4 or 2)
    constexpr int TNP = TN/2;    // packed pairs along n
    __shared__ __align__(16) float As[BK][72];      // A duplicated along m
    __shared__ __align__(16) float Bs[BK][BN+4];

    const int tid = threadIdx.x;
    const int tx = tid & 31, ty = tid >> 5;
    const int nBase = blockIdx.x * BN;
    const int mBase = blockIdx.y * 32;
    const int z = blockIdx.z;
    A0 += (size_t)z*zA; W0 += (size_t)z*zW; out += (size_t)z*zO;
    if (A1) A1 += (size_t)z*zA;
    if (W1) W1 += (size_t)z*zW;

    unsigned long long acc[4][TNP];
#pragma unroll
    for (int i = 0; i < 4; i++)
#pragma unroll
        for (int j = 0; j < TNP; j++) acc[i][j] = 0ull;

    const int npairs = (A1 != nullptr) ? 2 : 1;
    for (int p = 0; p < npairs; p++) {
        const float* __restrict__ A = (p == 0) ? A0 : A1;
        const float* __restrict__ W = (p == 0) ? W0 : W1;
        for (int k0 = 0; k0 < K; k0 += BK) {
            // stage A (32 x 16) duplicated along m
            for (int i = tid; i < 32*BK; i += 256) {
                int r = i >> 4, c = i & 15;
                float v = A[(size_t)(mBase + r)*lda + k0 + c];
                As[c][2*r] = v; As[c][2*r+1] = v;
            }
            // stage B -> Bs[k][n]
            if (BLAYN) {
                for (int i = tid; i < BN*BK; i += 256) {
                    int c = i / BN, n = i % BN;
                    int nn = nBase + n;
                    Bs[c][n] = (nn < N) ? W[(size_t)(k0 + c)*ldw + nn] : 0.f;
                }
            } else {
                for (int i = tid; i < BN*BK; i += 256) {
                    int r = i >> 4, c = i & 15;
                    int nn = nBase + r;
                    Bs[c][r] = (nn < N) ? W[(size_t)nn*ldw + k0 + c] : 0.f;
                }
            }
            __syncthreads();
#pragma unroll
            for (int k = 0; k < BK; k++) {
                const ulonglong2 a01 = *reinterpret_cast<const ulonglong2*>(&As[k][ty*8]);
                const ulonglong2 a23 = *reinterpret_cast<const ulonglong2*>(&As[k][ty*8+4]);
                unsigned long long av[4] = {a01.x, a01.y, a23.x, a23.y};
                unsigned long long bv[TNP];
                if constexpr (TNP == 2) {
                    ulonglong2 bb = *reinterpret_cast<const ulonglong2*>(&Bs[k][tx*4]);
                    bv[0] = bb.x; bv[1] = bb.y;
                } else {
                    bv[0] = *reinterpret_cast<const unsigned long long*>(&Bs[k][tx*2]);
                }
#pragma unroll
                for (int i = 0; i < 4; i++)
#pragma unroll
                    for (int j = 0; j < TNP; j++) fma2(acc[i][j], av[i], bv[j]);
            }
            __syncthreads();
        }
    }
#pragma unroll
    for (int i = 0; i < 4; i++) {
        int m = mBase + ty*4 + i;
#pragma unroll
        for (int j = 0; j < TNP; j++) {
            float2 v = unpk(acc[i][j]);
            int n = nBase + tx*TN + 2*j;
            float b0 = 0.f, b1 = 0.f;
            if (bias0) { if (n < N) b0 += bias0[n]; if (n+1 < N) b1 += bias0[n+1]; }
            if (bias1) { if (n < N) b0 += bias1[n]; if (n+1 < N) b1 += bias1[n+1]; }
            if (n   < N) out[(size_t)m*ldo + n]   = v.x + b0;
            if (n+1 < N) out[(size_t)m*ldo + n+1] = v.y + b1;
        }
    }
}

// ---------------- embedding + LayerNorm (unbiased std, eps on sd) ----------------
__global__ void __launch_bounds__(256) embed_ln_k(
    const int* __restrict__ tokens, const float* __restrict__ emb,
    const float* __restrict__ lg, const float* __restrict__ lb, int t)
{
    const int b = blockIdx.x, tid = threadIdx.x;
    const int tok = tokens[t*B_ + b];
    const float* __restrict__ row = emb + (size_t)tok * D_;
    float v[4]; float s = 0.f;
#pragma unroll
    for (int i = 0; i < 4; i++) { v[i] = row[tid + i*256]; s += v[i]; }
    __shared__ float red[256];
    red[tid] = s; __syncthreads();
    for (int o = 128; o > 0; o >>= 1) { if (tid < o) red[tid] += red[tid+o]; __syncthreads(); }
    const float mu = red[0] * (1.f/D_);
    __syncthreads();
    s = 0.f;
#pragma unroll
    for (int i = 0; i < 4; i++) { float d = v[i] - mu; s += d*d; }
    red[tid] = s; __syncthreads();
    for (int o = 128; o > 0; o >>= 1) { if (tid < o) red[tid] += red[tid+o]; __syncthreads(); }
    const float sd = sqrtf(red[0] / (float)(D_ - 1));
    const float inv = 1.f / (sd + EPS_);
#pragma unroll
    for (int i = 0; i < 4; i++) {
        int d = tid + i*256;
        g_e[(size_t)b*D_ + d] = v[i];
        g_eln[(size_t)b*D_ + d] = lg[d]*(v[i]-mu)*inv + lb[d];
    }
}

// ---------------- softmax over memory (per head,batch row), folds SCALE ----------------
__global__ void __launch_bounds__(256) softmax_k()
{
    const int hb = blockIdx.x, tid = threadIdx.x;
    const float* __restrict__ s = g_scores + (size_t)hb * MB;
    float* __restrict__ w = g_attnw + (size_t)hb * MB;
    __shared__ float red[256];
    float mx = -1e30f;
    for (int i = tid; i < MB; i += 256) mx = fmaxf(mx, s[i]);
    red[tid] = mx; __syncthreads();
    for (int o = 128; o > 0; o >>= 1) { if (tid < o) red[tid] = fmaxf(red[tid], red[tid+o]); __syncthreads(); }
    const float m2 = red[0] * SCALE_;
    __syncthreads();
    float sum = 0.f;
    for (int i = tid; i < MB; i += 256) { float e = expf(fmaf(s[i], SCALE_, -m2)); w[i] = e; sum += e; }
    red[tid] = sum; __syncthreads();
    for (int o = 128; o > 0; o >>= 1) { if (tid < o) red[tid] += red[tid+o]; __syncthreads(); }
    const float inv = 1.f / red[0];
    for (int i = tid; i < MB; i += 256) w[i] *= inv;
}

// ---------------- residual: h_att = e + att_out; hin[l] = h_prev[l] + h_att ----------------
__global__ void __launch_bounds__(256) resid_k()
{
    const int i = blockIdx.x*256 + threadIdx.x;
    const float ha = g_e[i] + g_o[i];
    g_hin[i]      = g_h[i]      + ha;
    g_hin[BD + i] = g_h[BD + i] + ha;
}

// ---------------- LSTM pointwise (gate order i,f,g,o) ----------------
__global__ void __launch_bounds__(256) lstm_pw_k(int l, int t)
{
    const int idx = blockIdx.x*256 + threadIdx.x;
    const int b = idx >> 10, d = idx & 1023;
    const float* __restrict__ gr = g_gates + (size_t)b*4*D_;
    const float ig = gr[d], fg = gr[D_+d], gg = gr[2*D_+d], og = gr[3*D_+d];
    const float c_old = g_c[(size_t)l*BD + idx];
    const float cn = sigf(fg)*c_old + sigf(ig)*tanhf(gg);
    const float hn = sigf(og)*tanhf(cn);
    g_h[(size_t)l*BD + idx] = hn;
    g_c[(size_t)l*BD + idx] = cn;
    g_histh[((size_t)t*L_ + l)*BD + idx] = hn;
    g_histc[((size_t)t*L_ + l)*BD + idx] = cn;
    if (l == L_-1) g_X[(size_t)t*BD + idx] = hn;
}

// ---------------- final state / memory gather ----------------
__global__ void __launch_bounds__(256) finalize_k(float* __restrict__ out)
{
    const int idx = blockIdx.x*256 + threadIdx.x;   // < L*MEM*BD
    const int l = idx / (MEM_*BD);
    const int r = idx % (MEM_*BD);
    const int m = r / BD, j = r % BD;
    const size_t src = ((size_t)(T_STEPS - MEM_ + m)*L_ + l)*BD + j;
    out[OFF_H + idx] = g_histh[src];
    out[OFF_C + idx] = g_histc[src];
    if (idx < L_*BD) {
        out[OFF_h + idx] = g_h[idx];
        out[OFF_c + idx] = g_c[idx];
    }
}

// ---------------- host ----------------
extern "C" void kernel_launch(void* const* d_in, const int* in_sizes, int n_in,
                              void* d_out, int out_size)
{
    const int*   tokens = (const int*)  d_in[0];
    const float* emb    = (const float*)d_in[1];
    const float* ln_g   = (const float*)d_in[2];
    const float* ln_b   = (const float*)d_in[3];
    const float* Wq     = (const float*)d_in[4];
    const float* bq     = (const float*)d_in[5];
    const float* Wk     = (const float*)d_in[6];
    const float* bk     = (const float*)d_in[7];
    const float* Wv     = (const float*)d_in[8];
    const float* bv     = (const float*)d_in[9];
    const float* Wo     = (const float*)d_in[10];
    const float* bo     = (const float*)d_in[11];
    const float* W_ih   = (const float*)d_in[12];
    const float* b_ih   = (const float*)d_in[13];
    const float* W_hh   = (const float*)d_in[14];
    const float* b_hh   = (const float*)d_in[15];
    const float* dec_W  = (const float*)d_in[16];
    const float* dec_b  = (const float*)d_in[17];
    const float* h0     = (const float*)d_in[18];
    const float* c0     = (const float*)d_in[19];
    const float* H0     = (const float*)d_in[20];
    // d_in[21] = C0: never observable in output (T >= MEM rolls it out)
    float* out = (float*)d_out;

    float *pe, *peln, *pq, *psc, *pw, *patt, *po, *phin, *ph, *pc, *pKC, *pVC, *pX, *pg;
    cudaGetSymbolAddress((void**)&pe,   g_e);
    cudaGetSymbolAddress((void**)&peln, g_eln);
    cudaGetSymbolAddress((void**)&pq,   g_q);
    cudaGetSymbolAddress((void**)&psc,  g_scores);
    cudaGetSymbolAddress((void**)&pw,   g_attnw);
    cudaGetSymbolAddress((void**)&patt, g_att);
    cudaGetSymbolAddress((void**)&po,   g_o);
    cudaGetSymbolAddress((void**)&phin, g_hin);
    cudaGetSymbolAddress((void**)&ph,   g_h);
    cudaGetSymbolAddress((void**)&pc,   g_c);
    cudaGetSymbolAddress((void**)&pKC,  g_KC);
    cudaGetSymbolAddress((void**)&pVC,  g_VC);
    cudaGetSymbolAddress((void**)&pX,   g_X);
    cudaGetSymbolAddress((void**)&pg,   g_gates);

    // init recurrent state
    cudaMemcpyAsync(ph, h0, (size_t)L_*BD*sizeof(float), cudaMemcpyDeviceToDevice);
    cudaMemcpyAsync(pc, c0, (size_t)L_*BD*sizeof(float), cudaMemcpyDeviceToDevice);

    // initial K/V cache from H0 layer 0: KC[m*B+b,:] = H0[0,m,b,:] @ Wk^T + bk
    gemm_k<128,false><<<dim3(8, MB/32, 1), 256>>>(H0, Wk, nullptr, nullptr, bk, nullptr,
        pKC, MB, D_, D_, D_, D_, D_, 0, 0, 0);
    gemm_k<128,false><<<dim3(8, MB/32, 1), 256>>>(H0, Wv, nullptr, nullptr, bv, nullptr,
        pVC, MB, D_, D_, D_, D_, D_, 0, 0, 0);

    for (int t = 0; t < T_STEPS; t++) {
        embed_ln_k<<<B_, 256>>>(tokens, emb, ln_g, ln_b, t);
        // q = LN(e) @ Wq^T + bq                                  [32,1024]
        gemm_k<128,false><<<dim3(8,1,1), 256>>>(peln, Wq, nullptr, nullptr, bq, nullptr,
            pq, B_, D_, D_, D_, D_, D_, 0, 0, 0);
        // scores[h,b,m] = sum_d q[b,h*DK+d]*KC[m,h*DK+d]         per-head GEMM
        gemm_k<128,false><<<dim3((MB+127)/128, 1, HEADS_), 256>>>(pq, pKC,
            nullptr, nullptr, nullptr, nullptr, psc,
            B_, MB, DK_, D_, D_, MB, DK_, DK_, B_*MB);
        softmax_k<<<HEADS_*B_, 256>>>();
        // att[b,h*DK+d] = sum_m attnw[h,b,m]*VC[m,h*DK+d]
        gemm_k<128,true><<<dim3(DK_/128, 1, HEADS_), 256>>>(pw, pVC,
            nullptr, nullptr, nullptr, nullptr, patt,
            B_, DK_, MB, MB, D_, D_, B_*MB, DK_, DK_);
        // o = att @ Wo^T + bo
        gemm_k<128,false><<<dim3(8,1,1), 256>>>(patt, Wo, nullptr, nullptr, bo, nullptr,
            po, B_, D_, D_, D_, D_, D_, 0, 0, 0);
        resid_k<<<BD/256, 256>>>();
        // LSTM layer 0: gates = e@W_ih[0]^T + b_ih[0] + hin[0]@W_hh[0]^T + b_hh[0]
        gemm_k<128,false><<<dim3(32,1,1), 256>>>(pe, W_ih, phin, W_hh,
            b_ih, b_hh, pg, B_, 4*D_, D_, D_, D_, 4*D_, 0, 0, 0);
        lstm_pw_k<<<BD/256, 256>>>(0, t);
        // LSTM layer 1: x = h[0] (this step), hidden = hin[1]
        gemm_k<128,false><<<dim3(32,1,1), 256>>>(ph, W_ih + (size_t)4*D_*D_,
            phin + BD, W_hh + (size_t)4*D_*D_,
            b_ih + 4*D_, b_hh + 4*D_, pg, B_, 4*D_, D_, D_, D_, 4*D_, 0, 0, 0);
        lstm_pw_k<<<BD/256, 256>>>(1, t);
        // K/V cache update: project new h[layer 0] into circular slot
        int slot = t % MEM_;
        gemm_k<128,false><<<dim3(8,1,1), 256>>>(ph, Wk, nullptr, nullptr, bk, nullptr,
            pKC + (size_t)slot*BD, B_, D_, D_, D_, D_, D_, 0, 0, 0);
        gemm_k<128,false><<<dim3(8,1,1), 256>>>(ph, Wv, nullptr, nullptr, bv, nullptr,
            pVC + (size_t)slot*BD, B_, D_, D_, D_, D_, D_, 0, 0, 0);
    }

    // batched decode: out[t*B+b, :] = X @ dec_W^T + dec_b       [2048, 32000]
    gemm_k<128,false><<<dim3(NTOK_/128, T_STEPS*B_/32, 1), 256>>>(pX, dec_W,
        nullptr, nullptr, dec_b, nullptr, out,
        T_STEPS*B_, NTOK_, D_, D_, D_, NTOK_, 0, 0, 0);

    finalize_k<<<(L_*MEM_*BD)/256, 256>>>(out);
}

// round 5
// speedup vs baseline: 3.9458x; 3.9458x over previous
#include <cuda_runtime.h>
#include <math.h>
#include <stdint.h>

// ---------------- problem constants ----------------
#define T_STEPS 64
#define B_      32
#define D_      1024
#define L_      2
#define MEM_    35
#define NTOK_   32000
#define HEADS_  2
#define DK_     512
#define BD      (B_*D_)            // 32768
#define MB      (MEM_*B_)          // 1120
#define EPS_    1e-6f
#define SCALE_  0.04419417382415922f  // 1/sqrt(512)
#define GRID    128

// output offsets (floats): decoded, h, c, H, C
#define OFF_h   ((size_t)T_STEPS*B_*NTOK_)
#define OFF_c   (OFF_h + (size_t)L_*BD)
#define OFF_H   (OFF_c + (size_t)L_*BD)
#define OFF_C   (OFF_H + (size_t)L_*MEM_*BD)

// ---------------- device scratch ----------------
__device__ float g_e[BD];
__device__ float g_eln[BD];
__device__ float g_q[BD];
__device__ float g_scores[HEADS_*B_*MB];
__device__ float g_attnw[HEADS_*B_*MB];
__device__ float g_att[BD];
__device__ float g_hin[L_*BD];
__device__ float g_gates[B_*4*D_];
__device__ float g_h[L_*BD];
__device__ float g_c[L_*BD];
__device__ float g_KC[MEM_*BD];
__device__ float g_VC[MEM_*BD];
__device__ float g_X[T_STEPS*BD];
__device__ float g_histh[T_STEPS*L_*BD];
__device__ float g_histc[T_STEPS*L_*BD];

__device__ unsigned g_bc;   // barrier arrive counter (returns to 0 each launch)
__device__ unsigned g_be;   // barrier epoch (monotonic across launches)

// ---------------- f32x2 helpers ----------------
__device__ __forceinline__ void fma2(unsigned long long &c, unsigned long long a,
                                     unsigned long long b) {
    asm("fma.rn.f32x2 %0, %1, %2, %0;" : "+l"(c) : "l"(a), "l"(b));
}
__device__ __forceinline__ float2 unpk(unsigned long long v) {
    float2 f;
    asm("mov.b64 {%0,%1}, %2;" : "=f"(f.x), "=f"(f.y) : "l"(v));
    return f;
}
__device__ __forceinline__ unsigned long long dupf(float w) {
    unsigned long long r;
    asm("mov.b64 %0, {%1,%1};" : "=l"(r) : "f"(w));
    return r;
}
__device__ __forceinline__ float sigf(float x) { return 1.f/(1.f+expf(-x)); }

// ---------------- grid barrier (epoch-based, replay-safe) ----------------
__device__ __forceinline__ void gbar(unsigned target) {
    __syncthreads();
    if (threadIdx.x == 0) {
        __threadfence();
        unsigned a = atomicAdd(&g_bc, 1);
        if (a == GRID - 1) {
            g_bc = 0;
            __threadfence();
            atomicAdd(&g_be, 1);
        } else {
            while (*(volatile unsigned*)&g_be != target) { }
        }
        __threadfence();
    }
    __syncthreads();
}

// ---------------- shared memory ----------------
struct SM { float As[64*36]; float Ws[64*33]; };
union SMU { SM g; float red[256]; };

// ---------------- 32x32 output tile GEMM (full K), FFMA2 inner ----------------
// blayn=false: contributes sum_k A[m,k] * W[(wrb+n), k]   (W row-major [N,K])
// blayn=true : contributes sum_k A[m,k] * W[k, wrb+n]     (W row-major [K,N])
// thread t: n = t&31, m = (t>>5)*4 .. +3. Accumulates into acc01/acc23.
__device__ void tile32_acc(
    const float* __restrict__ A, int lda,
    const float* __restrict__ W, int ldw, int wrb, bool blayn,
    int K, unsigned long long &acc01, unsigned long long &acc23, SM* sm)
{
    const int tid = threadIdx.x;
    const int tn  = tid & 31;
    const int wy4 = (tid >> 5) * 4;
    const int mA  = tid >> 3;          // staging row 0..31
    const int kA  = (tid & 7) * 8;     // staging k base 0..56

    for (int kc = 0; kc < K; kc += 64) {
        const int kl = min(64, K - kc);
        // ---- prefetch into registers ----
        float4 a0, a1, w0, w1;
        float wsc[8];
        if (kA < kl) {
            const float* Ar = A + (size_t)mA*lda + kc + kA;
            a0 = *(const float4*)Ar; a1 = *(const float4*)(Ar + 4);
        } else { a0 = make_float4(0,0,0,0); a1 = a0; }
        if (!blayn) {
            if (kA < kl) {
                const float* Wr = W + (size_t)(wrb + mA)*ldw + kc + kA;
                w0 = *(const float4*)Wr; w1 = *(const float4*)(Wr + 4);
            } else { w0 = make_float4(0,0,0,0); w1 = w0; }
        } else {
#pragma unroll
            for (int j = 0; j < 8; j++) {
                int i = tid + j*256, k = i >> 5, n = i & 31;
                wsc[j] = (k < kl) ? W[(size_t)(kc + k)*ldw + wrb + n] : 0.f;
            }
        }
        __syncthreads();
        // ---- store to smem (transposed, padded) ----
        sm->As[(kA+0)*36+mA] = a0.x; sm->As[(kA+1)*36+mA] = a0.y;
        sm->As[(kA+2)*36+mA] = a0.z; sm->As[(kA+3)*36+mA] = a0.w;
        sm->As[(kA+4)*36+mA] = a1.x; sm->As[(kA+5)*36+mA] = a1.y;
        sm->As[(kA+6)*36+mA] = a1.z; sm->As[(kA+7)*36+mA] = a1.w;
        if (!blayn) {
            sm->Ws[(kA+0)*33+mA] = w0.x; sm->Ws[(kA+1)*33+mA] = w0.y;
            sm->Ws[(kA+2)*33+mA] = w0.z; sm->Ws[(kA+3)*33+mA] = w0.w;
            sm->Ws[(kA+4)*33+mA] = w1.x; sm->Ws[(kA+5)*33+mA] = w1.y;
            sm->Ws[(kA+6)*33+mA] = w1.z; sm->Ws[(kA+7)*33+mA] = w1.w;
        } else {
#pragma unroll
            for (int j = 0; j < 8; j++) {
                int i = tid + j*256, k = i >> 5, n = i & 31;
                sm->Ws[k*33+n] = wsc[j];
            }
        }
        __syncthreads();
        // ---- compute 64 k ----
#pragma unroll 16
        for (int kk = 0; kk < 64; kk++) {
            double2 ad = *(const double2*)&sm->As[kk*36 + wy4];
            unsigned long long bw = dupf(sm->Ws[kk*33 + tn]);
            fma2(acc01, __double_as_longlong(ad.x), bw);
            fma2(acc23, __double_as_longlong(ad.y), bw);
        }
    }
}

// ---------------- the persistent 64-step kernel ----------------
__global__ void __launch_bounds__(256, 1) step_all_k(
    const int* __restrict__ tokens, const float* __restrict__ emb,
    const float* __restrict__ lg, const float* __restrict__ lb,
    const float* __restrict__ Wq, const float* __restrict__ bq,
    const float* __restrict__ Wk, const float* __restrict__ bk,
    const float* __restrict__ Wv, const float* __restrict__ bv,
    const float* __restrict__ Wo, const float* __restrict__ bo,
    const float* __restrict__ W_ih, const float* __restrict__ b_ih,
    const float* __restrict__ W_hh, const float* __restrict__ b_hh)
{
    __shared__ SMU smu;
    SM* sm = &smu.g;
    const int bid = blockIdx.x, tid = threadIdx.x;
    const int tn  = tid & 31;
    const int wy4 = (tid >> 5) * 4;

    const unsigned ebase = *(volatile unsigned*)&g_be;
    unsigned nb_ = 0;
#define GB() do { nb_++; gbar(ebase + nb_); } while (0)

    for (int t = 0; t < T_STEPS; t++) {
        // ---- Ph1: embed + LayerNorm ----
        if (bid < B_) {
            const int b = bid;
            const int tok = tokens[t*B_ + b];
            const float* __restrict__ row = emb + (size_t)tok * D_;
            float v[4]; float s = 0.f;
#pragma unroll
            for (int i = 0; i < 4; i++) { v[i] = row[tid + i*256]; s += v[i]; }
            smu.red[tid] = s; __syncthreads();
            for (int o = 128; o > 0; o >>= 1) { if (tid < o) smu.red[tid] += smu.red[tid+o]; __syncthreads(); }
            const float mu = smu.red[0] * (1.f/D_);
            __syncthreads();
            s = 0.f;
#pragma unroll
            for (int i = 0; i < 4; i++) { float d = v[i]-mu; s += d*d; }
            smu.red[tid] = s; __syncthreads();
            for (int o = 128; o > 0; o >>= 1) { if (tid < o) smu.red[tid] += smu.red[tid+o]; __syncthreads(); }
            const float inv = 1.f / (sqrtf(smu.red[0] / (float)(D_-1)) + EPS_);
            __syncthreads();
#pragma unroll
            for (int i = 0; i < 4; i++) {
                int d = tid + i*256;
                g_e[(size_t)b*D_ + d] = v[i];
                g_eln[(size_t)b*D_ + d] = lg[d]*(v[i]-mu)*inv + lb[d];
            }
        }
        GB();
        // ---- Ph2: q = LN(e) @ Wq^T + bq  (32 tiles) ----
        if (bid < 32) {
            const int nb = bid*32;
            unsigned long long a01 = 0, a23 = 0;
            tile32_acc(g_eln, D_, Wq, D_, nb, false, D_, a01, a23, sm);
            float2 v01 = unpk(a01), v23 = unpk(a23);
            const float bqv = bq[nb+tn];
            g_q[(size_t)(wy4+0)*D_ + nb+tn] = v01.x + bqv;
            g_q[(size_t)(wy4+1)*D_ + nb+tn] = v01.y + bqv;
            g_q[(size_t)(wy4+2)*D_ + nb+tn] = v23.x + bqv;
            g_q[(size_t)(wy4+3)*D_ + nb+tn] = v23.y + bqv;
        }
        GB();
        // ---- Ph3: scores[h,b,m] (70 tiles: 2 heads x 35) ----
        if (bid < HEADS_*35) {
            const int h = bid / 35, nb = (bid % 35)*32;
            unsigned long long a01 = 0, a23 = 0;
            tile32_acc(g_q + h*DK_, D_, g_KC + h*DK_, D_, nb, false, DK_, a01, a23, sm);
            float2 v01 = unpk(a01), v23 = unpk(a23);
            float* __restrict__ so = g_scores + (size_t)h*B_*MB + nb + tn;
            so[(size_t)(wy4+0)*MB] = v01.x;
            so[(size_t)(wy4+1)*MB] = v01.y;
            so[(size_t)(wy4+2)*MB] = v23.x;
            so[(size_t)(wy4+3)*MB] = v23.y;
        }
        GB();
        // ---- Ph4: softmax over memory (64 rows) ----
        if (bid < HEADS_*B_) {
            const float* __restrict__ s = g_scores + (size_t)bid * MB;
            float* __restrict__ w = g_attnw + (size_t)bid * MB;
            float mx = -1e30f;
            for (int i = tid; i < MB; i += 256) mx = fmaxf(mx, s[i]);
            smu.red[tid] = mx; __syncthreads();
            for (int o = 128; o > 0; o >>= 1) { if (tid < o) smu.red[tid] = fmaxf(smu.red[tid], smu.red[tid+o]); __syncthreads(); }
            const float m2 = smu.red[0] * SCALE_;
            __syncthreads();
            float sum = 0.f;
            for (int i = tid; i < MB; i += 256) { float e = expf(fmaf(s[i], SCALE_, -m2)); w[i] = e; sum += e; }
            smu.red[tid] = sum; __syncthreads();
            for (int o = 128; o > 0; o >>= 1) { if (tid < o) smu.red[tid] += smu.red[tid+o]; __syncthreads(); }
            const float inv = 1.f / smu.red[0];
            __syncthreads();
            for (int i = tid; i < MB; i += 256) w[i] *= inv;
        }
        GB();
        // ---- Ph5: att = attnw @ VC  (32 tiles: 2 heads x 16) ----
        if (bid < HEADS_*16) {
            const int h = bid / 16, nb = (bid % 16)*32;
            unsigned long long a01 = 0, a23 = 0;
            tile32_acc(g_attnw + (size_t)h*B_*MB, MB, g_VC + h*DK_, D_, nb, true, MB, a01, a23, sm);
            float2 v01 = unpk(a01), v23 = unpk(a23);
            float* __restrict__ ao = g_att + h*DK_ + nb + tn;
            ao[(size_t)(wy4+0)*D_] = v01.x;
            ao[(size_t)(wy4+1)*D_] = v01.y;
            ao[(size_t)(wy4+2)*D_] = v23.x;
            ao[(size_t)(wy4+3)*D_] = v23.y;
        }
        GB();
        // ---- Ph6: o = att @ Wo^T + bo ; hin[l] = h[l] + (e + o)  (32 tiles) ----
        if (bid < 32) {
            const int nb = bid*32;
            unsigned long long a01 = 0, a23 = 0;
            tile32_acc(g_att, D_, Wo, D_, nb, false, D_, a01, a23, sm);
            float2 v01 = unpk(a01), v23 = unpk(a23);
            const float bov = bo[nb+tn];
            float vv[4] = {v01.x+bov, v01.y+bov, v23.x+bov, v23.y+bov};
#pragma unroll
            for (int i = 0; i < 4; i++) {
                size_t idx = (size_t)(wy4+i)*D_ + nb + tn;
                float ha = g_e[idx] + vv[i];
                g_hin[idx]      = g_h[idx]      + ha;
                g_hin[BD + idx] = g_h[BD + idx] + ha;
            }
        }
        GB();
        // ---- Ph7: gates L0 = e@Wih0^T + hin0@Whh0^T + biases  (128 tiles) ----
        {
            const int nb = bid*32;
            unsigned long long a01 = 0, a23 = 0;
            tile32_acc(g_e,   D_, W_ih, D_, nb, false, D_, a01, a23, sm);
            tile32_acc(g_hin, D_, W_hh, D_, nb, false, D_, a01, a23, sm);
            float2 v01 = unpk(a01), v23 = unpk(a23);
            const float bb = b_ih[nb+tn] + b_hh[nb+tn];
            g_gates[(size_t)(wy4+0)*4*D_ + nb+tn] = v01.x + bb;
            g_gates[(size_t)(wy4+1)*4*D_ + nb+tn] = v01.y + bb;
            g_gates[(size_t)(wy4+2)*4*D_ + nb+tn] = v23.x + bb;
            g_gates[(size_t)(wy4+3)*4*D_ + nb+tn] = v23.y + bb;
        }
        GB();
        // ---- Ph8: LSTM pointwise L0 (128 blocks x 256 = BD) ----
        {
            const int idx = bid*256 + tid;
            const int b = idx >> 10, d = idx & 1023;
            const float* __restrict__ gr = g_gates + (size_t)b*4*D_;
            const float ig = gr[d], fg = gr[D_+d], gg = gr[2*D_+d], og = gr[3*D_+d];
            const float cn = sigf(fg)*g_c[idx] + sigf(ig)*tanhf(gg);
            const float hn = sigf(og)*tanhf(cn);
            g_h[idx] = hn; g_c[idx] = cn;
            g_histh[((size_t)t*L_)*BD + idx] = hn;
            g_histc[((size_t)t*L_)*BD + idx] = cn;
        }
        GB();
        // ---- Ph9: gates L1 = h0@Wih1^T + hin1@Whh1^T + biases ----
        {
            const int nb = bid*32;
            unsigned long long a01 = 0, a23 = 0;
            tile32_acc(g_h,        D_, W_ih + (size_t)4*D_*D_, D_, nb, false, D_, a01, a23, sm);
            tile32_acc(g_hin + BD, D_, W_hh + (size_t)4*D_*D_, D_, nb, false, D_, a01, a23, sm);
            float2 v01 = unpk(a01), v23 = unpk(a23);
            const float bb = b_ih[4*D_ + nb+tn] + b_hh[4*D_ + nb+tn];
            g_gates[(size_t)(wy4+0)*4*D_ + nb+tn] = v01.x + bb;
            g_gates[(size_t)(wy4+1)*4*D_ + nb+tn] = v01.y + bb;
            g_gates[(size_t)(wy4+2)*4*D_ + nb+tn] = v23.x + bb;
            g_gates[(size_t)(wy4+3)*4*D_ + nb+tn] = v23.y + bb;
        }
        GB();
        // ---- Ph10: LSTM pointwise L1 (+X history) ----
        {
            const int idx = bid*256 + tid;
            const int b = idx >> 10, d = idx & 1023;
            const float* __restrict__ gr = g_gates + (size_t)b*4*D_;
            const float ig = gr[d], fg = gr[D_+d], gg = gr[2*D_+d], og = gr[3*D_+d];
            const float cn = sigf(fg)*g_c[BD + idx] + sigf(ig)*tanhf(gg);
            const float hn = sigf(og)*tanhf(cn);
            g_h[BD + idx] = hn; g_c[BD + idx] = cn;
            g_histh[((size_t)t*L_ + 1)*BD + idx] = hn;
            g_histc[((size_t)t*L_ + 1)*BD + idx] = cn;
            g_X[(size_t)t*BD + idx] = hn;
        }
        GB();
        // ---- Ph11: KV cache update: project new h[0] into circular slot ----
        if (bid < 64) {
            const int slot = t % MEM_;
            const bool isK = bid < 32;
            const int nb = (bid & 31)*32;
            const float* Wx = isK ? Wk : Wv;
            const float* bx = isK ? bk : bv;
            float* outc = (isK ? g_KC : g_VC) + (size_t)slot*BD;
            unsigned long long a01 = 0, a23 = 0;
            tile32_acc(g_h, D_, Wx, D_, nb, false, D_, a01, a23, sm);
            float2 v01 = unpk(a01), v23 = unpk(a23);
            const float bxv = bx[nb+tn];
            outc[(size_t)(wy4+0)*D_ + nb+tn] = v01.x + bxv;
            outc[(size_t)(wy4+1)*D_ + nb+tn] = v01.y + bxv;
            outc[(size_t)(wy4+2)*D_ + nb+tn] = v23.x + bxv;
            outc[(size_t)(wy4+3)*D_ + nb+tn] = v23.y + bxv;
        }
        GB();
    }
#undef GB
}

// ---------------- standalone fp32 GEMM (KV init + decode) ----------------
#define BK 16
template<int BN, bool BLAYN>
__global__ void __launch_bounds__(256) gemm_k(
    const float* __restrict__ A0, const float* __restrict__ W0,
    const float* __restrict__ bias0, float* __restrict__ out,
    int M, int N, int K, int lda, int ldw, int ldo)
{
    constexpr int TN  = BN/32;
    constexpr int TNP = TN/2;
    __shared__ __align__(16) float As[BK][72];
    __shared__ __align__(16) float Bs[BK][BN+4];
    const int tid = threadIdx.x;
    const int tx = tid & 31, ty = tid >> 5;
    const int nBase = blockIdx.x * BN;
    const int mBase = blockIdx.y * 32;
    unsigned long long acc[4][TNP];
#pragma unroll
    for (int i = 0; i < 4; i++)
#pragma unroll
        for (int j = 0; j < TNP; j++) acc[i][j] = 0ull;
    for (int k0 = 0; k0 < K; k0 += BK) {
        for (int i = tid; i < 32*BK; i += 256) {
            int r = i >> 4, c = i & 15;
            float v = A0[(size_t)(mBase + r)*lda + k0 + c];
            As[c][2*r] = v; As[c][2*r+1] = v;
        }
        for (int i = tid; i < BN*BK; i += 256) {
            int r = i >> 4, c = i & 15;
            int nn = nBase + r;
            Bs[c][r] = (nn < N) ? W0[(size_t)nn*ldw + k0 + c] : 0.f;
        }
        __syncthreads();
#pragma unroll
        for (int k = 0; k < BK; k++) {
            const ulonglong2 a01 = *reinterpret_cast<const ulonglong2*>(&As[k][ty*8]);
            const ulonglong2 a23 = *reinterpret_cast<const ulonglong2*>(&As[k][ty*8+4]);
            unsigned long long av[4] = {a01.x, a01.y, a23.x, a23.y};
            unsigned long long bv[TNP];
            if constexpr (TNP == 2) {
                ulonglong2 bb = *reinterpret_cast<const ulonglong2*>(&Bs[k][tx*4]);
                bv[0] = bb.x; bv[1] = bb.y;
            } else {
                bv[0] = *reinterpret_cast<const unsigned long long*>(&Bs[k][tx*2]);
            }
#pragma unroll
            for (int i = 0; i < 4; i++)
#pragma unroll
                for (int j = 0; j < TNP; j++) fma2(acc[i][j], av[i], bv[j]);
        }
        __syncthreads();
    }
#pragma unroll
    for (int i = 0; i < 4; i++) {
        int m = mBase + ty*4 + i;
#pragma unroll
        for (int j = 0; j < TNP; j++) {
            float2 v = unpk(acc[i][j]);
            int n = nBase + tx*TN + 2*j;
            if (n   < N) out[(size_t)m*ldo + n]   = v.x + (bias0 ? bias0[n]   : 0.f);
            if (n+1 < N) out[(size_t)m*ldo + n+1] = v.y + (bias0 ? bias0[n+1] : 0.f);
        }
    }
}

// ---------------- final state / memory gather ----------------
__global__ void __launch_bounds__(256) finalize_k(float* __restrict__ out)
{
    const int idx = blockIdx.x*256 + threadIdx.x;
    const int l = idx / (MEM_*BD);
    const int r = idx % (MEM_*BD);
    const int m = r / BD, j = r % BD;
    const size_t src = ((size_t)(T_STEPS - MEM_ + m)*L_ + l)*BD + j;
    out[OFF_H + idx] = g_histh[src];
    out[OFF_C + idx] = g_histc[src];
    if (idx < L_*BD) {
        out[OFF_h + idx] = g_h[idx];
        out[OFF_c + idx] = g_c[idx];
    }
}

// ---------------- host ----------------
extern "C" void kernel_launch(void* const* d_in, const int* in_sizes, int n_in,
                              void* d_out, int out_size)
{
    const int*   tokens = (const int*)  d_in[0];
    const float* emb    = (const float*)d_in[1];
    const float* ln_g   = (const float*)d_in[2];
    const float* ln_b   = (const float*)d_in[3];
    const float* Wq     = (const float*)d_in[4];
    const float* bq     = (const float*)d_in[5];
    const float* Wk     = (const float*)d_in[6];
    const float* bk     = (const float*)d_in[7];
    const float* Wv     = (const float*)d_in[8];
    const float* bv     = (const float*)d_in[9];
    const float* Wo     = (const float*)d_in[10];
    const float* bo     = (const float*)d_in[11];
    const float* W_ih   = (const float*)d_in[12];
    const float* b_ih   = (const float*)d_in[13];
    const float* W_hh   = (const float*)d_in[14];
    const float* b_hh   = (const float*)d_in[15];
    const float* dec_W  = (const float*)d_in[16];
    const float* dec_b  = (const float*)d_in[17];
    const float* h0     = (const float*)d_in[18];
    const float* c0     = (const float*)d_in[19];
    const float* H0     = (const float*)d_in[20];
    float* out = (float*)d_out;

    float *ph, *pc, *pKC, *pVC, *pX;
    cudaGetSymbolAddress((void**)&ph,  g_h);
    cudaGetSymbolAddress((void**)&pc,  g_c);
    cudaGetSymbolAddress((void**)&pKC, g_KC);
    cudaGetSymbolAddress((void**)&pVC, g_VC);
    cudaGetSymbolAddress((void**)&pX,  g_X);

    cudaMemcpyAsync(ph, h0, (size_t)L_*BD*sizeof(float), cudaMemcpyDeviceToDevice);
    cudaMemcpyAsync(pc, c0, (size_t)L_*BD*sizeof(float), cudaMemcpyDeviceToDevice);

    // initial K/V cache from H0 layer 0
    gemm_k<128,false><<<dim3(8, MB/32, 1), 256>>>(H0, Wk, bk, pKC, MB, D_, D_, D_, D_, D_);
    gemm_k<128,false><<<dim3(8, MB/32, 1), 256>>>(H0, Wv, bv, pVC, MB, D_, D_, D_, D_, D_);

    // persistent 64-step kernel
    step_all_k<<<GRID, 256>>>(tokens, emb, ln_g, ln_b, Wq, bq, Wk, bk, Wv, bv,
                              Wo, bo, W_ih, b_ih, W_hh, b_hh);

    // batched decode: [2048, 32000]
    gemm_k<128,false><<<dim3(NTOK_/128, T_STEPS*B_/32, 1), 256>>>(pX, dec_W, dec_b, out,
        T_STEPS*B_, NTOK_, D_, D_, D_, NTOK_);

    finalize_k<<<(L_*MEM_*BD)/256, 256>>>(out);
}